// round 7
// baseline (speedup 1.0000x reference)
#include <cuda_runtime.h>
#include <cuda_fp16.h>
#include <cstdint>
#include <math.h>

#define NT   2048
#define DIM  2048
#define FFN_ 768
#define NE   64
#define TOPK 8
#define NP   (NT*TOPK)
#define CAP  512

#define STG     3
#define STAGEB  32768                  // A 16KB + B 16KB per stage
#define SMEM_DYN (STG*STAGEB)

// ---------------- scratch ----------------------------------------------------
__device__ int    g_cnt[NE];
__device__ int    g_tok[NE*CAP];
__device__ int    g_eid[NP];
__device__ int    g_slot[NP];
__device__ float  g_scr[NP];
__device__ __half g_xh[(size_t)NT*DIM];       // 8 MB, fp16 tokens
__device__ __half g_h[(size_t)NE*CAP*FFN_];   // 50 MB, fp16 activations
__device__ float  g_y[(size_t)NE*CAP*DIM];    // 268 MB

// ---------------- helpers ----------------------------------------------------
__device__ __forceinline__ uint32_t smem_u32(const void* p) {
    uint32_t a;
    asm("{ .reg .u64 t; cvta.to.shared.u64 t, %1; cvt.u32.u64 %0, t; }" : "=r"(a) : "l"(p));
    return a;
}
__device__ __forceinline__ void ldsm4(uint32_t* r, uint32_t addr) {
    asm volatile("ldmatrix.sync.aligned.m8n8.x4.shared.b16 {%0,%1,%2,%3}, [%4];"
                 : "=r"(r[0]), "=r"(r[1]), "=r"(r[2]), "=r"(r[3]) : "r"(addr));
}
__device__ __forceinline__ void mma16816(float* d, const uint32_t* a, const uint32_t* b) {
    asm volatile("mma.sync.aligned.m16n8k16.row.col.f32.f16.f16.f32 "
                 "{%0,%1,%2,%3}, {%4,%5,%6,%7}, {%8,%9}, {%0,%1,%2,%3};"
                 : "+f"(d[0]), "+f"(d[1]), "+f"(d[2]), "+f"(d[3])
                 : "r"(a[0]), "r"(a[1]), "r"(a[2]), "r"(a[3]), "r"(b[0]), "r"(b[1]));
}
__device__ __forceinline__ uint32_t pack2(float a, float b) {
    __half2 h = __floats2half2_rn(a, b);
    return *reinterpret_cast<uint32_t*>(&h);
}
__device__ __forceinline__ float silu_(float g) { return g / (1.f + __expf(-g)); }

#define CP16(s, g) asm volatile("cp.async.cg.shared.global [%0], [%1], 16;" :: "r"(s), "l"(g))
#define CPCOMMIT() asm volatile("cp.async.commit_group;" ::: "memory")
#define CPWAIT1()  asm volatile("cp.async.wait_group 1;" ::: "memory")

// ---------------- K0: x -> fp16 ----------------------------------------------
__global__ __launch_bounds__(256) void k_xh(const float* __restrict__ x) {
    size_t i = ((size_t)blockIdx.x * 256 + threadIdx.x) * 4;
    float4 v = *(const float4*)(x + i);
    uint2 p; p.x = pack2(v.x, v.y); p.y = pack2(v.z, v.w);
    *(uint2*)(g_xh + i) = p;
}

// ---------------- K1: gating (fp32 exact) ------------------------------------
__global__ __launch_bounds__(256) void k_gate(const float* __restrict__ x,
                                              const float* __restrict__ gw) {
    __shared__ float sx[4][DIM];
    __shared__ float slog[4][NE];
    const int t0 = blockIdx.x * 4;
    const int tid = threadIdx.x;
    for (int i = tid; i < 4 * (DIM / 4); i += 256) {
        int row = i / (DIM / 4), c = i % (DIM / 4);
        ((float4*)sx[row])[c] = ((const float4*)(x + (size_t)(t0 + row) * DIM))[c];
    }
    __syncthreads();
    const int warp = tid >> 5, lane = tid & 31;
    for (int d = warp * 32; d < warp * 32 + 32; d++) {
        int tk = d >> 6, e = d & 63;
        const float* w = gw + (size_t)e * DIM;
        float acc = 0.f;
        for (int i = lane * 4; i < DIM; i += 128) {
            float4 xv = *(const float4*)&sx[tk][i];
            float4 wv = *(const float4*)&w[i];
            acc += xv.x * wv.x + xv.y * wv.y + xv.z * wv.z + xv.w * wv.w;
        }
        #pragma unroll
        for (int o = 16; o; o >>= 1) acc += __shfl_xor_sync(0xffffffffu, acc, o);
        if (lane == 0) slog[tk][e] = acc;
    }
    __syncthreads();
    if (tid < 4) {
        const int tk = tid, token = t0 + tk;
        float m = -1e30f;
        for (int e = 0; e < NE; e++) m = fmaxf(m, slog[tk][e]);
        float pr[NE], s = 0.f;
        for (int e = 0; e < NE; e++) { pr[e] = __expf(slog[tk][e] - m); s += pr[e]; }
        const float inv = 1.f / s;
        for (int k = 0; k < TOPK; k++) {
            float best = -1.f; int be = 0;
            for (int e = 0; e < NE; e++) if (pr[e] > best) { best = pr[e]; be = e; }
            g_eid[token * TOPK + k] = be;
            g_scr[token * TOPK + k] = best * inv;
            pr[be] = -2.f;
        }
    }
}

// ---------------- K2: routing ------------------------------------------------
__global__ void k_zero() { if (threadIdx.x < NE) g_cnt[threadIdx.x] = 0; }
__global__ void k_route() {
    int p = blockIdx.x * 256 + threadIdx.x;
    if (p >= NP) return;
    int e = g_eid[p];
    int slot = atomicAdd(&g_cnt[e], 1);
    g_slot[p] = slot;
    if (slot < CAP) g_tok[e * CAP + slot] = p >> 3;
}

// ============ shared 128x128 fp16 MMA mainloop (3-stage cp.async) ============
// A: fp16 rows in gmem (asrc[4]: per-thread row ptrs, 16B chunk each, chunk
//    q = tid + 256*i -> row q>>3, chunk q&7). B: fp32 rows (bsrc[4] chunk ptrs),
// packed to fp16 in regs. smem stage: A[128x64 f16 | 16KB] B[128x64 f16 | 16KB].
struct Frag { float a[4][4][4]; };

__device__ __forceinline__ void mainloop(
    uint8_t* sm, uint32_t sbase,
    const __half* (&asrc)[4], const float* (&bsrc)[4],
    uint32_t (&offa)[4], uint32_t (&offb)[4],
    int wm, int wn, int lane, int NK, Frag& F)
{
    #pragma unroll
    for (int a = 0; a < 4; a++)
        #pragma unroll
        for (int b = 0; b < 4; b++)
            #pragma unroll
            for (int c = 0; c < 4; c++) F.a[a][b][c] = 0.f;

    // prologue: A(0), A(1) via cp.async; B(0) direct; B(1) in regs
    #pragma unroll
    for (int s = 0; s < 2; s++) {
        #pragma unroll
        for (int i = 0; i < 4; i++)
            CP16(sbase + s * STAGEB + offa[i], asrc[i] + s * 64);
        CPCOMMIT();
    }
    #pragma unroll
    for (int i = 0; i < 4; i++) {
        float4 u = *(const float4*)(bsrc[i]);
        float4 v = *(const float4*)(bsrc[i] + 4);
        uint4 p; p.x = pack2(u.x, u.y); p.y = pack2(u.z, u.w);
        p.z = pack2(v.x, v.y); p.w = pack2(v.z, v.w);
        *(uint4*)(sm + 16384 + offb[i]) = p;
    }
    float4 vb[4][2];
    #pragma unroll
    for (int i = 0; i < 4; i++) {
        vb[i][0] = *(const float4*)(bsrc[i] + 64);
        vb[i][1] = *(const float4*)(bsrc[i] + 68);
    }

    const uint32_t sA0 = sbase, sB0 = sbase + 16384;
    #pragma unroll 1
    for (int j = 0; j < NK; j++) {
        const int cur = j % STG, nxt = (j + 1) % STG, nx2 = (j + 2) % STG;
        CPWAIT1();
        __syncthreads();
        // issue A(j+2)
        if (j + 2 < NK) {
            #pragma unroll
            for (int i = 0; i < 4; i++)
                CP16(sbase + nx2 * STAGEB + offa[i], asrc[i] + (j + 2) * 64);
        }
        CPCOMMIT();                                   // exactly one group per iter
        // STS B(j+1)
        if (j + 1 < NK) {
            #pragma unroll
            for (int i = 0; i < 4; i++) {
                uint4 p;
                p.x = pack2(vb[i][0].x, vb[i][0].y); p.y = pack2(vb[i][0].z, vb[i][0].w);
                p.z = pack2(vb[i][1].x, vb[i][1].y); p.w = pack2(vb[i][1].z, vb[i][1].w);
                *(uint4*)(sm + nxt * STAGEB + 16384 + offb[i]) = p;
            }
        }
        // LDG B(j+2)
        if (j + 2 < NK) {
            #pragma unroll
            for (int i = 0; i < 4; i++) {
                vb[i][0] = *(const float4*)(bsrc[i] + (j + 2) * 64);
                vb[i][1] = *(const float4*)(bsrc[i] + (j + 2) * 64 + 4);
            }
        }
        // MMA(j)
        const uint32_t sA = sA0 + cur * STAGEB, sB = sB0 + cur * STAGEB;
        #pragma unroll
        for (int ks = 0; ks < 4; ks++) {
            uint32_t af[4][4], bf[2][4];
            #pragma unroll
            for (int mt = 0; mt < 4; mt++) {
                int row = wm * 64 + mt * 16 + (lane & 15);
                int byt = ks * 32 + ((lane >> 4) << 4);
                ldsm4(af[mt], sA + row * 128 + (byt ^ ((row & 7) << 4)));
            }
            #pragma unroll
            for (int n2 = 0; n2 < 2; n2++) {
                int row = wn * 32 + n2 * 16 + ((lane >> 4) << 3) + (lane & 7);
                int byt = ks * 32 + (((lane >> 3) & 1) << 4);
                ldsm4(bf[n2], sB + row * 128 + (byt ^ ((row & 7) << 4)));
            }
            #pragma unroll
            for (int mt = 0; mt < 4; mt++)
                #pragma unroll
                for (int nt = 0; nt < 4; nt++)
                    mma16816(F.a[mt][nt], af[mt], &bf[nt >> 1][(nt & 1) * 2]);
        }
    }
}

// ---------------- K3: gate/up GEMM + SwiGLU ----------------------------------
__global__ __launch_bounds__(256, 1) void k_gateup_mma(const float* __restrict__ wg,
                                                       const float* __restrict__ wu) {
    extern __shared__ __align__(1024) uint8_t sm[];
    const int e = blockIdx.z;
    int nrows = g_cnt[e]; if (nrows > CAP) nrows = CAP;
    const int row0 = blockIdx.y * 128;
    if (row0 >= nrows) return;
    const int f0 = blockIdx.x * 64;

    const int tid = threadIdx.x;
    const int wid = tid >> 5, lane = tid & 31;
    const int wm = wid & 1, wn = wid >> 1;
    const uint32_t sbase = smem_u32(sm);

    const __half* asrc[4]; const float* bsrc[4];
    uint32_t offa[4], offb[4];
    #pragma unroll
    for (int i = 0; i < 4; i++) {
        int q = tid + 256 * i;
        int r = q >> 3, c = q & 7;
        int rr = row0 + r;
        int tok = g_tok[e * CAP + (rr < nrows ? rr : 0)];
        asrc[i] = g_xh + (size_t)tok * DIM + c * 8;
        offa[i] = r * 128 + ((c * 16) ^ ((r & 7) << 4));
        // B row r: interleaved gate/up n-tiles of 8
        int t8 = r >> 3, w8 = r & 7;
        int fr = f0 + (t8 >> 1) * 8 + w8;
        const float* wb = (t8 & 1) ? wu : wg;
        bsrc[i] = wb + ((size_t)e * FFN_ + fr) * DIM + c * 8;
        offb[i] = offa[i];
    }

    Frag F;
    mainloop(sm, sbase, asrc, bsrc, offa, offb, wm, wn, lane, DIM / 64, F);

    const int qrow = lane >> 2, qcol = (lane & 3) * 2;
    #pragma unroll
    for (int mt = 0; mt < 4; mt++) {
        int mbase = row0 + wm * 64 + mt * 16;
        #pragma unroll
        for (int p = 0; p < 2; p++) {
            int fbase = f0 + (wn * 2 + p) * 8 + qcol;
            float* gA = F.a[mt][2 * p];
            float* uA = F.a[mt][2 * p + 1];
            int r0 = mbase + qrow, r1 = mbase + qrow + 8;
            if (r0 < nrows) {
                __half2 h = __floats2half2_rn(silu_(gA[0]) * uA[0], silu_(gA[1]) * uA[1]);
                *(__half2*)&g_h[((size_t)e * CAP + r0) * FFN_ + fbase] = h;
            }
            if (r1 < nrows) {
                __half2 h = __floats2half2_rn(silu_(gA[2]) * uA[2], silu_(gA[3]) * uA[3]);
                *(__half2*)&g_h[((size_t)e * CAP + r1) * FFN_ + fbase] = h;
            }
        }
    }
}

// ---------------- K4: down GEMM ----------------------------------------------
__global__ __launch_bounds__(256, 1) void k_down_mma(const float* __restrict__ wd) {
    extern __shared__ __align__(1024) uint8_t sm[];
    const int e = blockIdx.z;
    int nrows = g_cnt[e]; if (nrows > CAP) nrows = CAP;
    const int row0 = blockIdx.y * 128;
    if (row0 >= nrows) return;
    const int d0 = blockIdx.x * 128;

    const int tid = threadIdx.x;
    const int wid = tid >> 5, lane = tid & 31;
    const int wm = wid & 1, wn = wid >> 1;
    const uint32_t sbase = smem_u32(sm);

    const __half* asrc[4]; const float* bsrc[4];
    uint32_t offa[4], offb[4];
    #pragma unroll
    for (int i = 0; i < 4; i++) {
        int q = tid + 256 * i;
        int r = q >> 3, c = q & 7;
        asrc[i] = g_h + ((size_t)e * CAP + row0 + r) * FFN_ + c * 8;
        bsrc[i] = wd + ((size_t)e * DIM + d0 + r) * FFN_ + c * 8;
        offa[i] = r * 128 + ((c * 16) ^ ((r & 7) << 4));
        offb[i] = offa[i];
    }

    Frag F;
    mainloop(sm, sbase, asrc, bsrc, offa, offb, wm, wn, lane, FFN_ / 64, F);

    const int qrow = lane >> 2, qcol = (lane & 3) * 2;
    #pragma unroll
    for (int mt = 0; mt < 4; mt++) {
        int mbase = row0 + wm * 64 + mt * 16;
        #pragma unroll
        for (int nt = 0; nt < 4; nt++) {
            int dcol = d0 + wn * 32 + nt * 8 + qcol;
            int r0 = mbase + qrow, r1 = mbase + qrow + 8;
            if (r0 < nrows) {
                float2 v = make_float2(F.a[mt][nt][0], F.a[mt][nt][1]);
                *(float2*)&g_y[((size_t)e * CAP + r0) * DIM + dcol] = v;
            }
            if (r1 < nrows) {
                float2 v = make_float2(F.a[mt][nt][2], F.a[mt][nt][3]);
                *(float2*)&g_y[((size_t)e * CAP + r1) * DIM + dcol] = v;
            }
        }
    }
}

// ---------------- K5: weighted combine ---------------------------------------
__global__ __launch_bounds__(256) void k_combine(float* __restrict__ out) {
    const int t = blockIdx.x;
    const int tid = threadIdx.x;
    float4 acc0 = make_float4(0.f, 0.f, 0.f, 0.f);
    float4 acc1 = make_float4(0.f, 0.f, 0.f, 0.f);
    #pragma unroll
    for (int k = 0; k < TOPK; k++) {
        const int p = t * TOPK + k;
        const int e = g_eid[p];
        const int s = g_slot[p];
        if (s >= CAP) continue;
        const float sc = g_scr[p];
        const float4* yr = (const float4*)&g_y[((size_t)e * CAP + s) * DIM];
        float4 v0 = yr[tid];
        float4 v1 = yr[tid + 256];
        acc0.x += sc * v0.x; acc0.y += sc * v0.y; acc0.z += sc * v0.z; acc0.w += sc * v0.w;
        acc1.x += sc * v1.x; acc1.y += sc * v1.y; acc1.z += sc * v1.z; acc1.w += sc * v1.w;
    }
    float4* op = (float4*)(out + (size_t)t * DIM);
    op[tid] = acc0;
    op[tid + 256] = acc1;
}

// ---------------- launch -----------------------------------------------------
extern "C" void kernel_launch(void* const* d_in, const int* in_sizes, int n_in,
                              void* d_out, int out_size) {
    (void)in_sizes; (void)n_in; (void)out_size;
    const float* x      = (const float*)d_in[0];
    const float* gate_w = (const float*)d_in[1];
    const float* w_gate = (const float*)d_in[2];
    const float* w_up   = (const float*)d_in[3];
    const float* w_down = (const float*)d_in[4];
    float* out          = (float*)d_out;

    cudaFuncSetAttribute(k_gateup_mma, cudaFuncAttributeMaxDynamicSharedMemorySize, SMEM_DYN);
    cudaFuncSetAttribute(k_down_mma,   cudaFuncAttributeMaxDynamicSharedMemorySize, SMEM_DYN);

    k_gate<<<NT / 4, 256>>>(x, gate_w);
    k_xh<<<(NT * DIM) / 1024, 256>>>(x);
    k_zero<<<1, 64>>>();
    k_route<<<NP / 256, 256>>>();
    k_gateup_mma<<<dim3(FFN_ / 64, CAP / 128, NE), 256, SMEM_DYN>>>(w_gate, w_up);
    k_down_mma<<<dim3(DIM / 128, CAP / 128, NE), 256, SMEM_DYN>>>(w_down);
    k_combine<<<NT, 256>>>(out);
}